// round 3
// baseline (speedup 1.0000x reference)
#include <cuda_runtime.h>
#include <math.h>

#define NTOK   4096
#define DMODEL 256
#define NHEAD  8
#define HDIM   32
#define QKVDIM (3 * DMODEL)   // 768

// Scratch (allocation-free rule: __device__ globals)
__device__ __align__(16) float g_qkv[NTOK * QKVDIM];    // [N, 768] = Q|K|V
__device__ __align__(16) float g_attn[NTOK * DMODEL];   // [N, 256] attention out (pre-proj)
__device__ __align__(16) float g_delta[NTOK * DMODEL];  // [N, 256] projected delta

// ---------------------------------------------------------------------------
// GEMM: C[M,Nc] = A[M,K] @ B[Nc,K]^T + bias[Nc]
// BM=128, BN=64, BK=16, 256 threads, each thread computes 8x4.
// M multiple of 128, Nc multiple of 64, K multiple of 16 (no guards needed).
// ---------------------------------------------------------------------------
__global__ __launch_bounds__(256) void gemm_bias_kernel(
    const float* __restrict__ A, const float* __restrict__ B,
    const float* __restrict__ bias, float* __restrict__ C,
    int Nc, int K)
{
    __shared__ __align__(16) float As[16][128];
    __shared__ __align__(16) float Bs[16][64];

    const int tid  = threadIdx.x;
    const int tr   = tid >> 4;   // 0..15 -> rows tr*8..tr*8+7
    const int tc   = tid & 15;   // 0..15 -> cols tc*4..tc*4+3
    const int row0 = blockIdx.y * 128;
    const int col0 = blockIdx.x * 64;

    float acc[8][4];
#pragma unroll
    for (int i = 0; i < 8; i++)
#pragma unroll
        for (int j = 0; j < 4; j++) acc[i][j] = 0.f;

    for (int kt = 0; kt < K; kt += 16) {
        // Load A tile (128x16) transposed into As[k][row]
#pragma unroll
        for (int i = 0; i < 2; i++) {
            int idx = tid + (i << 8);        // 0..511
            int r   = idx >> 2;              // 0..127
            int kq  = idx & 3;               // float4 index within the 16-wide k slab
            float4 v = *(const float4*)(A + (size_t)(row0 + r) * K + kt + (kq << 2));
            As[(kq << 2) + 0][r] = v.x;
            As[(kq << 2) + 1][r] = v.y;
            As[(kq << 2) + 2][r] = v.z;
            As[(kq << 2) + 3][r] = v.w;
        }
        // Load B tile (64x16) transposed into Bs[k][col]
        {
            int r  = tid >> 2;               // 0..63
            int kq = tid & 3;
            float4 v = *(const float4*)(B + (size_t)(col0 + r) * K + kt + (kq << 2));
            Bs[(kq << 2) + 0][r] = v.x;
            Bs[(kq << 2) + 1][r] = v.y;
            Bs[(kq << 2) + 2][r] = v.z;
            Bs[(kq << 2) + 3][r] = v.w;
        }
        __syncthreads();

#pragma unroll
        for (int k = 0; k < 16; k++) {
            float a[8], b[4];
            float4 a0 = *(const float4*)&As[k][tr * 8];
            float4 a1 = *(const float4*)&As[k][tr * 8 + 4];
            a[0] = a0.x; a[1] = a0.y; a[2] = a0.z; a[3] = a0.w;
            a[4] = a1.x; a[5] = a1.y; a[6] = a1.z; a[7] = a1.w;
            float4 bv = *(const float4*)&Bs[k][tc * 4];
            b[0] = bv.x; b[1] = bv.y; b[2] = bv.z; b[3] = bv.w;
#pragma unroll
            for (int i = 0; i < 8; i++)
#pragma unroll
                for (int j = 0; j < 4; j++)
                    acc[i][j] += a[i] * b[j];
        }
        __syncthreads();
    }

    float4 bv = *(const float4*)&bias[col0 + tc * 4];
#pragma unroll
    for (int i = 0; i < 8; i++) {
        float4 o;
        o.x = acc[i][0] + bv.x;
        o.y = acc[i][1] + bv.y;
        o.z = acc[i][2] + bv.z;
        o.w = acc[i][3] + bv.w;
        *(float4*)(C + (size_t)(row0 + tr * 8 + i) * Nc + col0 + tc * 4) = o;
    }
}

// ---------------------------------------------------------------------------
// Block-diagonal flash attention.
// batch_idx is sorted, so the attention set of row n is the contiguous range
// [lower_bound(b), lower_bound(b+1)). Grid: (N/128, H), 128 threads,
// 1 query per thread. K/V tiles of 32 keys staged in smem; inner smem reads
// are warp-uniform (broadcast, conflict-free).
// ---------------------------------------------------------------------------
__device__ __forceinline__ int lb_search(const int* __restrict__ a, int n, int v)
{
    int lo = 0, hi = n;
    while (lo < hi) {
        int mid = (lo + hi) >> 1;
        if (a[mid] < v) lo = mid + 1; else hi = mid;
    }
    return lo;
}

__global__ __launch_bounds__(128) void attn_kernel(
    const float* __restrict__ qkv, const int* __restrict__ bidx,
    float* __restrict__ out)
{
    __shared__ __align__(16) float Ks[32][32];
    __shared__ __align__(16) float Vs[32][32];
    __shared__ int sh_range[2];

    const int h   = blockIdx.y;
    const int tid = threadIdx.x;
    const int n   = blockIdx.x * 128 + tid;

    const int b = bidx[n];
    const int s = lb_search(bidx, NTOK, b);
    const int e = lb_search(bidx, NTOK, b + 1);
    if (tid == 0)   sh_range[0] = s;   // sorted => thread 0 has the min start
    if (tid == 127) sh_range[1] = e;   // thread 127 has the max end

    // Pre-scaled query in registers
    const float scale = 0.1767766952966368811f;  // 1/sqrt(32)
    float q[32];
    {
        const float* qp = qkv + (size_t)n * QKVDIM + h * HDIM;
#pragma unroll
        for (int i = 0; i < 8; i++) {
            float4 v = *(const float4*)(qp + i * 4);
            q[i * 4 + 0] = v.x * scale;
            q[i * 4 + 1] = v.y * scale;
            q[i * 4 + 2] = v.z * scale;
            q[i * 4 + 3] = v.w * scale;
        }
    }

    float o[32];
#pragma unroll
    for (int d = 0; d < 32; d++) o[d] = 0.f;
    float m = -1e30f, l = 0.f;

    __syncthreads();
    const int smin = sh_range[0];
    const int emax = sh_range[1];

    for (int kt = smin; kt < emax; kt += 32) {
        // Cooperative K/V tile load: 32 rows x 32 dims each
#pragma unroll
        for (int i = 0; i < 2; i++) {
            int idx = tid + (i << 7);        // 0..255
            int r   = idx >> 3;              // 0..31
            int d4  = idx & 7;               // float4 lane within the 32-dim row
            int kr  = kt + r;
            if (kr < NTOK) {
                const float* kp = qkv + (size_t)kr * QKVDIM + DMODEL + h * HDIM + (d4 << 2);
                *(float4*)&Ks[r][d4 << 2] = *(const float4*)kp;
                *(float4*)&Vs[r][d4 << 2] = *(const float4*)(kp + DMODEL);  // V block
            }
        }
        __syncthreads();

        int jlo = s - kt; if (jlo < 0)  jlo = 0;
        int jhi = e - kt; if (jhi > 32) jhi = 32;
        for (int j = jlo; j < jhi; j++) {
            float sc = 0.f;
            const float4* kp4 = (const float4*)Ks[j];
#pragma unroll
            for (int i = 0; i < 8; i++) {
                float4 kv = kp4[i];
                sc += q[i * 4 + 0] * kv.x + q[i * 4 + 1] * kv.y
                    + q[i * 4 + 2] * kv.z + q[i * 4 + 3] * kv.w;
            }
            if (sc > m) {                      // rescale only on new max
                float corr = __expf(m - sc);
                l *= corr;
#pragma unroll
                for (int d = 0; d < 32; d++) o[d] *= corr;
                m = sc;
            }
            float p = __expf(sc - m);
            l += p;
            const float4* vp4 = (const float4*)Vs[j];
#pragma unroll
            for (int i = 0; i < 8; i++) {
                float4 vv = vp4[i];
                o[i * 4 + 0] += p * vv.x;
                o[i * 4 + 1] += p * vv.y;
                o[i * 4 + 2] += p * vv.z;
                o[i * 4 + 3] += p * vv.w;
            }
        }
        __syncthreads();
    }

    const float inv = 1.f / l;   // l > 0: every row attends to itself
    float* op = out + (size_t)n * DMODEL + h * HDIM;
#pragma unroll
    for (int i = 0; i < 8; i++) {
        float4 v;
        v.x = o[i * 4 + 0] * inv;
        v.y = o[i * 4 + 1] * inv;
        v.z = o[i * 4 + 2] * inv;
        v.w = o[i * 4 + 3] * inv;
        *(float4*)(op + i * 4) = v;
    }
}

// ---------------------------------------------------------------------------
// Fused residual + LayerNorm. Warp per row (8 elems/lane), 8 rows per block.
// ---------------------------------------------------------------------------
__global__ __launch_bounds__(256) void ln_kernel(
    const float* __restrict__ x, const float* __restrict__ delta,
    const float* __restrict__ gamma, const float* __restrict__ beta,
    float* __restrict__ out)
{
    const int row  = blockIdx.x * 8 + (threadIdx.x >> 5);
    const int lane = threadIdx.x & 31;

    const float4* xp = (const float4*)(x + (size_t)row * DMODEL);
    const float4* dp = (const float4*)(delta + (size_t)row * DMODEL);

    float4 a = xp[lane],      bb = dp[lane];
    float4 v0 = make_float4(a.x + bb.x, a.y + bb.y, a.z + bb.z, a.w + bb.w);
    a = xp[lane + 32]; bb = dp[lane + 32];
    float4 v1 = make_float4(a.x + bb.x, a.y + bb.y, a.z + bb.z, a.w + bb.w);

    float sum = v0.x + v0.y + v0.z + v0.w + v1.x + v1.y + v1.z + v1.w;
#pragma unroll
    for (int off = 16; off; off >>= 1) sum += __shfl_xor_sync(0xffffffffu, sum, off);
    const float mean = sum * (1.f / 256.f);

    float sq = (v0.x - mean) * (v0.x - mean) + (v0.y - mean) * (v0.y - mean)
             + (v0.z - mean) * (v0.z - mean) + (v0.w - mean) * (v0.w - mean)
             + (v1.x - mean) * (v1.x - mean) + (v1.y - mean) * (v1.y - mean)
             + (v1.z - mean) * (v1.z - mean) + (v1.w - mean) * (v1.w - mean);
#pragma unroll
    for (int off = 16; off; off >>= 1) sq += __shfl_xor_sync(0xffffffffu, sq, off);
    const float rstd = rsqrtf(sq * (1.f / 256.f) + 1e-5f);

    float4 g = ((const float4*)gamma)[lane];
    float4 bt = ((const float4*)beta)[lane];
    float4 r0;
    r0.x = (v0.x - mean) * rstd * g.x + bt.x;
    r0.y = (v0.y - mean) * rstd * g.y + bt.y;
    r0.z = (v0.z - mean) * rstd * g.z + bt.z;
    r0.w = (v0.w - mean) * rstd * g.w + bt.w;
    g  = ((const float4*)gamma)[lane + 32];
    bt = ((const float4*)beta)[lane + 32];
    float4 r1;
    r1.x = (v1.x - mean) * rstd * g.x + bt.x;
    r1.y = (v1.y - mean) * rstd * g.y + bt.y;
    r1.z = (v1.z - mean) * rstd * g.z + bt.z;
    r1.w = (v1.w - mean) * rstd * g.w + bt.w;

    float4* op = (float4*)(out + (size_t)row * DMODEL);
    op[lane]      = r0;
    op[lane + 32] = r1;
}

// ---------------------------------------------------------------------------
// Launch (graph-capturable: kernel launches on default stream only)
// ---------------------------------------------------------------------------
extern "C" void kernel_launch(void* const* d_in, const int* in_sizes, int n_in,
                              void* d_out, int out_size)
{
    const float* slots  = (const float*)d_in[0];   // [1, 4096, 256]
    const int*   bidx   = (const int*)  d_in[1];   // [4096] sorted
    const float* w_in   = (const float*)d_in[2];   // [768, 256]
    const float* b_in   = (const float*)d_in[3];   // [768]
    const float* w_out  = (const float*)d_in[4];   // [256, 256]
    const float* b_out  = (const float*)d_in[5];   // [256]
    const float* ln_g   = (const float*)d_in[6];   // [256]
    const float* ln_b   = (const float*)d_in[7];   // [256]
    float*       out    = (float*)d_out;           // [1, 4096, 256]

    float *qkv, *attn, *delta;
    cudaGetSymbolAddress((void**)&qkv,   g_qkv);
    cudaGetSymbolAddress((void**)&attn,  g_attn);
    cudaGetSymbolAddress((void**)&delta, g_delta);

    // 1) QKV = x @ w_in^T + b_in          [4096, 768]
    {
        dim3 grid(QKVDIM / 64, NTOK / 128);
        gemm_bias_kernel<<<grid, 256>>>(slots, w_in, b_in, qkv, QKVDIM, DMODEL);
    }
    // 2) Block-diagonal attention         [4096, 256]
    {
        dim3 grid(NTOK / 128, NHEAD);
        attn_kernel<<<grid, 128>>>(qkv, bidx, attn);
    }
    // 3) delta = attn @ w_out^T + b_out   [4096, 256]
    {
        dim3 grid(DMODEL / 64, NTOK / 128);
        gemm_bias_kernel<<<grid, 256>>>(attn, w_out, b_out, delta, DMODEL, DMODEL);
    }
    // 4) out = LayerNorm(x + delta)
    ln_kernel<<<NTOK / 8, 256>>>(slots, delta, ln_g, ln_b, out);
}

// round 7
// speedup vs baseline: 1.0759x; 1.0759x over previous
#include <cuda_runtime.h>
#include <cuda_bf16.h>
#include <cstdint>
#include <math.h>

#define NTOK   4096
#define DMODEL 256
#define NHEAD  8
#define HDIM   32
#define QKVDIM (3 * DMODEL)   // 768

// ---------------------------------------------------------------------------
// Scratch (allocation-free rule: __device__ globals)
// ---------------------------------------------------------------------------
__device__ __align__(16) float g_qkv[NTOK * QKVDIM];        // fp32 QKV
__device__ __align__(16) float g_attn[NTOK * DMODEL];       // attention out
__device__ __align__(16) float g_delta[NTOK * DMODEL];      // projected delta
// bf16 split operands
__device__ __align__(16) __nv_bfloat16 g_xh[NTOK * DMODEL];
__device__ __align__(16) __nv_bfloat16 g_xl[NTOK * DMODEL];
__device__ __align__(16) __nv_bfloat16 g_wih[QKVDIM * DMODEL];
__device__ __align__(16) __nv_bfloat16 g_wil[QKVDIM * DMODEL];
__device__ __align__(16) __nv_bfloat16 g_woh[DMODEL * DMODEL];
__device__ __align__(16) __nv_bfloat16 g_wol[DMODEL * DMODEL];
__device__ __align__(16) __nv_bfloat16 g_ah[NTOK * DMODEL];
__device__ __align__(16) __nv_bfloat16 g_al[NTOK * DMODEL];

// ---------------------------------------------------------------------------
// fp32 -> (bf16 hi, bf16 lo) split. Processes 4 floats / thread.
// ---------------------------------------------------------------------------
__global__ __launch_bounds__(256) void split_bf16_kernel(
    const float* __restrict__ in, __nv_bfloat16* __restrict__ hi,
    __nv_bfloat16* __restrict__ lo, int n4)
{
    int i = blockIdx.x * blockDim.x + threadIdx.x;
    if (i >= n4) return;
    float4 v = ((const float4*)in)[i];
    __nv_bfloat16 h0 = __float2bfloat16(v.x), h1 = __float2bfloat16(v.y);
    __nv_bfloat16 h2 = __float2bfloat16(v.z), h3 = __float2bfloat16(v.w);
    __nv_bfloat16 l0 = __float2bfloat16(v.x - __bfloat162float(h0));
    __nv_bfloat16 l1 = __float2bfloat16(v.y - __bfloat162float(h1));
    __nv_bfloat16 l2 = __float2bfloat16(v.z - __bfloat162float(h2));
    __nv_bfloat16 l3 = __float2bfloat16(v.w - __bfloat162float(h3));
    __nv_bfloat162 hp0(h0, h1), hp1(h2, h3), lp0(l0, l1), lp1(l2, l3);
    uint2 hv, lv;
    hv.x = *(uint32_t*)&hp0; hv.y = *(uint32_t*)&hp1;
    lv.x = *(uint32_t*)&lp0; lv.y = *(uint32_t*)&lp1;
    ((uint2*)hi)[i] = hv;
    ((uint2*)lo)[i] = lv;
}

// ---------------------------------------------------------------------------
// Warp-MMA GEMM (portable HMMA: mma.sync.m16n8k16 bf16, fp32 accum) with
// bf16 hi/lo split operands (3 passes: Ah*Bh + Ah*Bl + Al*Bh).
// C[M,Nc] = A[M,256] @ B[Nc,256]^T + bias.
// Block 256 thr (8 warps), tile 128x64; warp tile 32x32 = 2x4 m16n8k16 tiles.
// K=256 fully staged in smem, padded row stride 264 bf16 (528 B) so every
// 32-bit fragment load is bank-conflict-free.
// ---------------------------------------------------------------------------
#define KSTR 264                      // smem row stride in bf16 elems
#define ROWB (KSTR * 2)               // 528 bytes
#define SM_AH 0
#define SM_AL (SM_AH + 128 * ROWB)    // 67584
#define SM_BH (SM_AL + 128 * ROWB)    // 135168
#define SM_BL (SM_BH + 64 * ROWB)     // 168960
#define SM_TOTAL (SM_BL + 64 * ROWB)  // 202752 bytes

__device__ __forceinline__ void mma_bf16(float* c, const uint32_t* a, const uint32_t* b)
{
    asm volatile(
        "mma.sync.aligned.m16n8k16.row.col.f32.bf16.bf16.f32 "
        "{%0,%1,%2,%3}, {%4,%5,%6,%7}, {%8,%9}, {%0,%1,%2,%3};"
        : "+f"(c[0]), "+f"(c[1]), "+f"(c[2]), "+f"(c[3])
        : "r"(a[0]), "r"(a[1]), "r"(a[2]), "r"(a[3]), "r"(b[0]), "r"(b[1]));
}

__global__ __launch_bounds__(256) void mma_gemm_kernel(
    const __nv_bfloat16* __restrict__ Ah, const __nv_bfloat16* __restrict__ Al,
    const __nv_bfloat16* __restrict__ Bh, const __nv_bfloat16* __restrict__ Bl,
    const float* __restrict__ bias, float* __restrict__ C, int Nc)
{
    extern __shared__ __align__(16) char sm[];
    const int tid  = threadIdx.x;
    const int wid  = tid >> 5;
    const int lane = tid & 31;
    const int g    = lane >> 2;      // 0..7
    const int t4   = lane & 3;       // 0..3
    const int row0 = blockIdx.y * 128;
    const int col0 = blockIdx.x * 64;
    const int wm   = (wid & 3) * 32; // warp row offset within tile
    const int wn   = (wid >> 2) * 32;

    // --- Stage A (128x256, hi+lo) and B (64x256, hi+lo) into smem ---
    for (int c = tid; c < 4096; c += 256) {
        int r = c >> 5, kc = c & 31;
        uint32_t off = (uint32_t)r * ROWB + (uint32_t)kc * 16;
        size_t gi = (size_t)(row0 + r) * 256 + ((size_t)kc << 3);
        *(uint4*)(sm + SM_AH + off) = *(const uint4*)(Ah + gi);
        *(uint4*)(sm + SM_AL + off) = *(const uint4*)(Al + gi);
    }
    for (int c = tid; c < 2048; c += 256) {
        int r = c >> 5, kc = c & 31;
        uint32_t off = (uint32_t)r * ROWB + (uint32_t)kc * 16;
        size_t gi = (size_t)(col0 + r) * 256 + ((size_t)kc << 3);
        *(uint4*)(sm + SM_BH + off) = *(const uint4*)(Bh + gi);
        *(uint4*)(sm + SM_BL + off) = *(const uint4*)(Bl + gi);
    }
    __syncthreads();

    float acc[2][4][4];
#pragma unroll
    for (int mi = 0; mi < 2; mi++)
#pragma unroll
        for (int ni = 0; ni < 4; ni++)
#pragma unroll
            for (int k = 0; k < 4; k++) acc[mi][ni][k] = 0.f;

    // Base byte offsets of this thread's fragment elements (k = 0 column)
    // A frag element (row, k): sm + base + row*ROWB + k*2
    const uint32_t a_row = (uint32_t)(wm + g);
    const uint32_t b_row = (uint32_t)(wn + g);
    const uint32_t kb0   = (uint32_t)(t4 * 4);   // 2*t4 bf16 elems = 4 bytes

#pragma unroll 1
    for (int p = 0; p < 3; p++) {
        const char* Ab = sm + ((p == 2) ? SM_AL : SM_AH);
        const char* Bb = sm + ((p == 1) ? SM_BL : SM_BH);
#pragma unroll 4
        for (int s = 0; s < 16; s++) {
            const uint32_t kb = (uint32_t)(s * 32) + kb0;  // byte offset along K
            uint32_t af[2][4], bf[4][2];
#pragma unroll
            for (int mi = 0; mi < 2; mi++) {
                const char* ap = Ab + (a_row + mi * 16) * ROWB + kb;
                af[mi][0] = *(const uint32_t*)(ap);
                af[mi][1] = *(const uint32_t*)(ap + 8 * ROWB);
                af[mi][2] = *(const uint32_t*)(ap + 16);
                af[mi][3] = *(const uint32_t*)(ap + 8 * ROWB + 16);
            }
#pragma unroll
            for (int ni = 0; ni < 4; ni++) {
                const char* bp = Bb + (b_row + ni * 8) * ROWB + kb;
                bf[ni][0] = *(const uint32_t*)(bp);
                bf[ni][1] = *(const uint32_t*)(bp + 16);
            }
#pragma unroll
            for (int mi = 0; mi < 2; mi++)
#pragma unroll
                for (int ni = 0; ni < 4; ni++)
                    mma_bf16(acc[mi][ni], af[mi], bf[ni]);
        }
    }

    // --- Epilogue: add bias, store fp32 ---
#pragma unroll
    for (int mi = 0; mi < 2; mi++) {
        const int r0 = row0 + wm + mi * 16 + g;
#pragma unroll
        for (int ni = 0; ni < 4; ni++) {
            const int col = col0 + wn + ni * 8 + t4 * 2;
            const float bx = bias[col], by = bias[col + 1];
            float2 v0 = make_float2(acc[mi][ni][0] + bx, acc[mi][ni][1] + by);
            float2 v1 = make_float2(acc[mi][ni][2] + bx, acc[mi][ni][3] + by);
            *(float2*)(C + (size_t)r0 * Nc + col)       = v0;
            *(float2*)(C + (size_t)(r0 + 8) * Nc + col) = v1;
        }
    }
}

// ---------------------------------------------------------------------------
// Block-diagonal flash attention (unchanged from R3). batch_idx sorted =>
// attention set of row n is [lower_bound(b), lower_bound(b+1)).
// ---------------------------------------------------------------------------
__device__ __forceinline__ int lb_search(const int* __restrict__ a, int n, int v)
{
    int lo = 0, hi = n;
    while (lo < hi) {
        int mid = (lo + hi) >> 1;
        if (a[mid] < v) lo = mid + 1; else hi = mid;
    }
    return lo;
}

__global__ __launch_bounds__(128) void attn_kernel(
    const float* __restrict__ qkv, const int* __restrict__ bidx,
    float* __restrict__ out)
{
    __shared__ __align__(16) float Ks[32][32];
    __shared__ __align__(16) float Vs[32][32];
    __shared__ int sh_range[2];

    const int h   = blockIdx.y;
    const int tid = threadIdx.x;
    const int n   = blockIdx.x * 128 + tid;

    const int b = bidx[n];
    const int s = lb_search(bidx, NTOK, b);
    const int e = lb_search(bidx, NTOK, b + 1);
    if (tid == 0)   sh_range[0] = s;
    if (tid == 127) sh_range[1] = e;

    const float scale = 0.1767766952966368811f;  // 1/sqrt(32)
    float q[32];
    {
        const float* qp = qkv + (size_t)n * QKVDIM + h * HDIM;
#pragma unroll
        for (int i = 0; i < 8; i++) {
            float4 v = *(const float4*)(qp + i * 4);
            q[i * 4 + 0] = v.x * scale;
            q[i * 4 + 1] = v.y * scale;
            q[i * 4 + 2] = v.z * scale;
            q[i * 4 + 3] = v.w * scale;
        }
    }

    float o[32];
#pragma unroll
    for (int d = 0; d < 32; d++) o[d] = 0.f;
    float m = -1e30f, l = 0.f;

    __syncthreads();
    const int smin = sh_range[0];
    const int emax = sh_range[1];

    for (int kt = smin; kt < emax; kt += 32) {
#pragma unroll
        for (int i = 0; i < 2; i++) {
            int idx = tid + (i << 7);
            int r   = idx >> 3;
            int d4  = idx & 7;
            int kr  = kt + r;
            if (kr < NTOK) {
                const float* kp = qkv + (size_t)kr * QKVDIM + DMODEL + h * HDIM + (d4 << 2);
                *(float4*)&Ks[r][d4 << 2] = *(const float4*)kp;
                *(float4*)&Vs[r][d4 << 2] = *(const float4*)(kp + DMODEL);
            }
        }
        __syncthreads();

        int jlo = s - kt; if (jlo < 0)  jlo = 0;
        int jhi = e - kt; if (jhi > 32) jhi = 32;
        for (int j = jlo; j < jhi; j++) {
            float sc = 0.f;
            const float4* kp4 = (const float4*)Ks[j];
#pragma unroll
            for (int i = 0; i < 8; i++) {
                float4 kv = kp4[i];
                sc += q[i * 4 + 0] * kv.x + q[i * 4 + 1] * kv.y
                    + q[i * 4 + 2] * kv.z + q[i * 4 + 3] * kv.w;
            }
            if (sc > m) {
                float corr = __expf(m - sc);
                l *= corr;
#pragma unroll
                for (int d = 0; d < 32; d++) o[d] *= corr;
                m = sc;
            }
            float p = __expf(sc - m);
            l += p;
            const float4* vp4 = (const float4*)Vs[j];
#pragma unroll
            for (int i = 0; i < 8; i++) {
                float4 vv = vp4[i];
                o[i * 4 + 0] += p * vv.x;
                o[i * 4 + 1] += p * vv.y;
                o[i * 4 + 2] += p * vv.z;
                o[i * 4 + 3] += p * vv.w;
            }
        }
        __syncthreads();
    }

    const float inv = 1.f / l;
    float* op = out + (size_t)n * DMODEL + h * HDIM;
#pragma unroll
    for (int i = 0; i < 8; i++) {
        float4 v;
        v.x = o[i * 4 + 0] * inv;
        v.y = o[i * 4 + 1] * inv;
        v.z = o[i * 4 + 2] * inv;
        v.w = o[i * 4 + 3] * inv;
        *(float4*)(op + i * 4) = v;
    }
}

// ---------------------------------------------------------------------------
// Fused residual + LayerNorm (unchanged from R3)
// ---------------------------------------------------------------------------
__global__ __launch_bounds__(256) void ln_kernel(
    const float* __restrict__ x, const float* __restrict__ delta,
    const float* __restrict__ gamma, const float* __restrict__ beta,
    float* __restrict__ out)
{
    const int row  = blockIdx.x * 8 + (threadIdx.x >> 5);
    const int lane = threadIdx.x & 31;

    const float4* xp = (const float4*)(x + (size_t)row * DMODEL);
    const float4* dp = (const float4*)(delta + (size_t)row * DMODEL);

    float4 a = xp[lane],      bb = dp[lane];
    float4 v0 = make_float4(a.x + bb.x, a.y + bb.y, a.z + bb.z, a.w + bb.w);
    a = xp[lane + 32]; bb = dp[lane + 32];
    float4 v1 = make_float4(a.x + bb.x, a.y + bb.y, a.z + bb.z, a.w + bb.w);

    float sum = v0.x + v0.y + v0.z + v0.w + v1.x + v1.y + v1.z + v1.w;
#pragma unroll
    for (int off = 16; off; off >>= 1) sum += __shfl_xor_sync(0xffffffffu, sum, off);
    const float mean = sum * (1.f / 256.f);

    float sq = (v0.x - mean) * (v0.x - mean) + (v0.y - mean) * (v0.y - mean)
             + (v0.z - mean) * (v0.z - mean) + (v0.w - mean) * (v0.w - mean)
             + (v1.x - mean) * (v1.x - mean) + (v1.y - mean) * (v1.y - mean)
             + (v1.z - mean) * (v1.z - mean) + (v1.w - mean) * (v1.w - mean);
#pragma unroll
    for (int off = 16; off; off >>= 1) sq += __shfl_xor_sync(0xffffffffu, sq, off);
    const float rstd = rsqrtf(sq * (1.f / 256.f) + 1e-5f);

    float4 g = ((const float4*)gamma)[lane];
    float4 bt = ((const float4*)beta)[lane];
    float4 r0;
    r0.x = (v0.x - mean) * rstd * g.x + bt.x;
    r0.y = (v0.y - mean) * rstd * g.y + bt.y;
    r0.z = (v0.z - mean) * rstd * g.z + bt.z;
    r0.w = (v0.w - mean) * rstd * g.w + bt.w;
    g  = ((const float4*)gamma)[lane + 32];
    bt = ((const float4*)beta)[lane + 32];
    float4 r1;
    r1.x = (v1.x - mean) * rstd * g.x + bt.x;
    r1.y = (v1.y - mean) * rstd * g.y + bt.y;
    r1.z = (v1.z - mean) * rstd * g.z + bt.z;
    r1.w = (v1.w - mean) * rstd * g.w + bt.w;

    float4* op = (float4*)(out + (size_t)row * DMODEL);
    op[lane]      = r0;
    op[lane + 32] = r1;
}

// ---------------------------------------------------------------------------
// Launch (graph-capturable: kernel launches on default stream only)
// ---------------------------------------------------------------------------
extern "C" void kernel_launch(void* const* d_in, const int* in_sizes, int n_in,
                              void* d_out, int out_size)
{
    const float* slots  = (const float*)d_in[0];   // [1, 4096, 256]
    const int*   bidx   = (const int*)  d_in[1];   // [4096] sorted
    const float* w_in   = (const float*)d_in[2];   // [768, 256]
    const float* b_in   = (const float*)d_in[3];   // [768]
    const float* w_out  = (const float*)d_in[4];   // [256, 256]
    const float* b_out  = (const float*)d_in[5];   // [256]
    const float* ln_g   = (const float*)d_in[6];   // [256]
    const float* ln_b   = (const float*)d_in[7];   // [256]
    float*       out    = (float*)d_out;           // [1, 4096, 256]

    float *qkv, *attn, *delta;
    __nv_bfloat16 *xh, *xl, *wih, *wil, *woh, *wol, *ah, *al;
    cudaGetSymbolAddress((void**)&qkv,   g_qkv);
    cudaGetSymbolAddress((void**)&attn,  g_attn);
    cudaGetSymbolAddress((void**)&delta, g_delta);
    cudaGetSymbolAddress((void**)&xh,  g_xh);
    cudaGetSymbolAddress((void**)&xl,  g_xl);
    cudaGetSymbolAddress((void**)&wih, g_wih);
    cudaGetSymbolAddress((void**)&wil, g_wil);
    cudaGetSymbolAddress((void**)&woh, g_woh);
    cudaGetSymbolAddress((void**)&wol, g_wol);
    cudaGetSymbolAddress((void**)&ah,  g_ah);
    cudaGetSymbolAddress((void**)&al,  g_al);

    cudaFuncSetAttribute(mma_gemm_kernel,
                         cudaFuncAttributeMaxDynamicSharedMemorySize, SM_TOTAL);

    // 0) fp32 -> bf16 hi/lo splits for X and weights
    {
        int n4 = NTOK * DMODEL / 4;
        split_bf16_kernel<<<(n4 + 255) / 256, 256>>>(slots, xh, xl, n4);
        int w4 = QKVDIM * DMODEL / 4;
        split_bf16_kernel<<<(w4 + 255) / 256, 256>>>(w_in, wih, wil, w4);
        int o4 = DMODEL * DMODEL / 4;
        split_bf16_kernel<<<(o4 + 255) / 256, 256>>>(w_out, woh, wol, o4);
    }
    // 1) QKV = x @ w_in^T + b_in   [4096, 768]  (HMMA, bf16x3 split)
    {
        dim3 grid(QKVDIM / 64, NTOK / 128);
        mma_gemm_kernel<<<grid, 256, SM_TOTAL>>>(xh, xl, wih, wil, b_in, qkv, QKVDIM);
    }
    // 2) Block-diagonal attention   [4096, 256]
    {
        dim3 grid(NTOK / 128, NHEAD);
        attn_kernel<<<grid, 128>>>(qkv, bidx, attn);
    }
    // 3) split attention output, then delta = attn @ w_out^T + b_out
    {
        int n4 = NTOK * DMODEL / 4;
        split_bf16_kernel<<<(n4 + 255) / 256, 256>>>(attn, ah, al, n4);
        dim3 grid(DMODEL / 64, NTOK / 128);
        mma_gemm_kernel<<<grid, 256, SM_TOTAL>>>(ah, al, woh, wol, b_out, delta, DMODEL);
    }
    // 4) out = LayerNorm(x + delta)
    ln_kernel<<<NTOK / 8, 256>>>(slots, delta, ln_g, ln_b, out);
}

// round 14
// speedup vs baseline: 1.5505x; 1.4412x over previous
#include <cuda_runtime.h>
#include <cuda_bf16.h>
#include <cstdint>
#include <math.h>

#define NTOK   4096
#define DMODEL 256
#define NHEAD  8
#define HDIM   32
#define QKVDIM (3 * DMODEL)   // 768

// ---------------------------------------------------------------------------
// Scratch (allocation-free rule: __device__ globals)
// ---------------------------------------------------------------------------
__device__ __align__(16) float g_qkv[NTOK * QKVDIM];    // fp32 QKV
__device__ __align__(16) float g_attn[NTOK * DMODEL];   // attention out
__device__ __align__(16) float g_delta[NTOK * DMODEL];  // projected delta

// ---------------------------------------------------------------------------
// GEMM v3: C[M,Nc] = A[M,256] @ B[Nc,256]^T + bias (A,B fp32 in gmem).
// bf16 hi/lo split fused into the loader (3 HMMA passes AhBh+AhBl+AlBh,
// fp32 accum). BM=128, BN=64, BK=64, SINGLE smem stage, phase loop; overlap
// across phases comes from 2 CTAs/SM. 256 threads, 8 warps, warp tile 32x32.
// Row stride 144 B: multiple of 16 (STS.128 alignment legal) and 144/4 = 36
// ≡ 4 (mod 32) keeps fragment LDS conflict-free.
// ---------------------------------------------------------------------------
#define SA_ROWB 144                       // smem row stride in bytes
#define ST_AH   0
#define ST_AL   (ST_AH + 128 * SA_ROWB)   // 18432
#define ST_BH   (ST_AL + 128 * SA_ROWB)   // 36864
#define ST_BL   (ST_BH + 64 * SA_ROWB)    // 46080
#define GM_SMEM (ST_BL + 64 * SA_ROWB)    // 55296 total

__device__ __forceinline__ void mma_bf16(float* c, const uint32_t* a, const uint32_t* b)
{
    asm volatile(
        "mma.sync.aligned.m16n8k16.row.col.f32.bf16.bf16.f32 "
        "{%0,%1,%2,%3}, {%4,%5,%6,%7}, {%8,%9}, {%0,%1,%2,%3};"
        : "+f"(c[0]), "+f"(c[1]), "+f"(c[2]), "+f"(c[3])
        : "r"(a[0]), "r"(a[1]), "r"(a[2]), "r"(a[3]), "r"(b[0]), "r"(b[1]));
}

__device__ __forceinline__ void split2(float a, float b, uint32_t& h, uint32_t& l)
{
    __nv_bfloat16 ha = __float2bfloat16(a), hb = __float2bfloat16(b);
    __nv_bfloat16 la = __float2bfloat16(a - __bfloat162float(ha));
    __nv_bfloat16 lb = __float2bfloat16(b - __bfloat162float(hb));
    __nv_bfloat162 hh(ha, hb), ll(la, lb);
    h = *(uint32_t*)&hh;
    l = *(uint32_t*)&ll;
}

__device__ __forceinline__ void split8(float4 f0, float4 f1, uint4& h, uint4& l)
{
    split2(f0.x, f0.y, h.x, l.x);
    split2(f0.z, f0.w, h.y, l.y);
    split2(f1.x, f1.y, h.z, l.z);
    split2(f1.z, f1.w, h.w, l.w);
}

__global__ __launch_bounds__(256, 2) void mma_gemm_kernel(
    const float* __restrict__ A, const float* __restrict__ B,
    const float* __restrict__ bias, float* __restrict__ C, int Nc)
{
    extern __shared__ __align__(16) char sm[];
    const int tid  = threadIdx.x;
    const int wid  = tid >> 5;
    const int lane = tid & 31;
    const int g    = lane >> 2;      // 0..7
    const int t4   = lane & 3;       // 0..3
    const int row0 = blockIdx.y * 128;
    const int col0 = blockIdx.x * 64;
    const int wm   = (wid & 3) * 32;
    const int wn   = (wid >> 2) * 32;

    float acc[2][4][4];
#pragma unroll
    for (int mi = 0; mi < 2; mi++)
#pragma unroll
        for (int ni = 0; ni < 4; ni++)
#pragma unroll
            for (int k = 0; k < 4; k++) acc[mi][ni][k] = 0.f;

    const uint32_t a_row = (uint32_t)(wm + g);
    const uint32_t b_row = (uint32_t)(wn + g);
    const uint32_t kb0   = (uint32_t)(t4 * 4);

    for (int it = 0; it < 4; it++) {
        const int kb = it * 64;

        // ---- load fp32 chunk, split to bf16 hi/lo, store to smem ----
        // A: 128 rows x 8 q-slots = 1024 pairs; 4 per thread (FULL coverage).
#pragma unroll
        for (int i = 0; i < 4; i++) {
            int p = tid + (i << 8);          // 0..1023
            int r = p >> 3, q = p & 7;
            const float* ga = A + (size_t)(row0 + r) * 256 + kb + q * 8;
            float4 v0 = *(const float4*)(ga);
            float4 v1 = *(const float4*)(ga + 4);
            uint4 h, l;
            split8(v0, v1, h, l);
            *(uint4*)(sm + ST_AH + r * SA_ROWB + q * 16) = h;
            *(uint4*)(sm + ST_AL + r * SA_ROWB + q * 16) = l;
        }
        // B: 64 rows x 8 q-slots = 512 pairs; 2 per thread (FULL coverage).
#pragma unroll
        for (int i = 0; i < 2; i++) {
            int p = tid + (i << 8);          // 0..511
            int r = p >> 3, q = p & 7;
            const float* gb = B + (size_t)(col0 + r) * 256 + kb + q * 8;
            float4 v0 = *(const float4*)(gb);
            float4 v1 = *(const float4*)(gb + 4);
            uint4 h, l;
            split8(v0, v1, h, l);
            *(uint4*)(sm + ST_BH + r * SA_ROWB + q * 16) = h;
            *(uint4*)(sm + ST_BL + r * SA_ROWB + q * 16) = l;
        }
        __syncthreads();

        // ---- MMAs on this chunk: 3 split passes x 4 K-steps ----
#pragma unroll
        for (int p = 0; p < 3; p++) {
            const char* Ab = sm + ((p == 2) ? ST_AL : ST_AH);
            const char* Bb = sm + ((p == 1) ? ST_BL : ST_BH);
#pragma unroll
            for (int st = 0; st < 4; st++) {
                const uint32_t kf = (uint32_t)(st * 32) + kb0;
                uint32_t af[2][4], bf[4][2];
#pragma unroll
                for (int mi = 0; mi < 2; mi++) {
                    const char* ap = Ab + (a_row + mi * 16) * SA_ROWB + kf;
                    af[mi][0] = *(const uint32_t*)(ap);
                    af[mi][1] = *(const uint32_t*)(ap + 8 * SA_ROWB);
                    af[mi][2] = *(const uint32_t*)(ap + 16);
                    af[mi][3] = *(const uint32_t*)(ap + 8 * SA_ROWB + 16);
                }
#pragma unroll
                for (int ni = 0; ni < 4; ni++) {
                    const char* bp = Bb + (b_row + ni * 8) * SA_ROWB + kf;
                    bf[ni][0] = *(const uint32_t*)(bp);
                    bf[ni][1] = *(const uint32_t*)(bp + 16);
                }
#pragma unroll
                for (int mi = 0; mi < 2; mi++)
#pragma unroll
                    for (int ni = 0; ni < 4; ni++)
                        mma_bf16(acc[mi][ni], af[mi], bf[ni]);
            }
        }
        __syncthreads();   // all reads done before next chunk overwrites
    }

    // --- Epilogue: add bias, store fp32 ---
#pragma unroll
    for (int mi = 0; mi < 2; mi++) {
        const int r0 = row0 + wm + mi * 16 + g;
#pragma unroll
        for (int ni = 0; ni < 4; ni++) {
            const int col = col0 + wn + ni * 8 + t4 * 2;
            const float bx = bias[col], by = bias[col + 1];
            float2 v0 = make_float2(acc[mi][ni][0] + bx, acc[mi][ni][1] + by);
            float2 v1 = make_float2(acc[mi][ni][2] + bx, acc[mi][ni][3] + by);
            *(float2*)(C + (size_t)r0 * Nc + col)       = v0;
            *(float2*)(C + (size_t)(r0 + 8) * Nc + col) = v1;
        }
    }
}

// ---------------------------------------------------------------------------
// Block-diagonal flash attention v2. batch_idx sorted => attention set of
// row n is [lower_bound(b), lower_bound(b+1)). 1 query/thread, 128 thr,
// 64-key tiles, 2-key unroll, 4 independent dot partials.
// ---------------------------------------------------------------------------
__device__ __forceinline__ int lb_search(const int* __restrict__ a, int n, int v)
{
    int lo = 0, hi = n;
    while (lo < hi) {
        int mid = (lo + hi) >> 1;
        if (a[mid] < v) lo = mid + 1; else hi = mid;
    }
    return lo;
}

__global__ __launch_bounds__(128) void attn_kernel(
    const float* __restrict__ qkv, const int* __restrict__ bidx,
    float* __restrict__ out)
{
    __shared__ __align__(16) float Ks[64][32];
    __shared__ __align__(16) float Vs[64][32];
    __shared__ int sh_range[2];

    const int h   = blockIdx.y;
    const int tid = threadIdx.x;
    const int n   = blockIdx.x * 128 + tid;

    const int b = bidx[n];
    const int s = lb_search(bidx, NTOK, b);
    const int e = lb_search(bidx, NTOK, b + 1);
    if (tid == 0)   sh_range[0] = s;   // sorted => thread 0 has min start
    if (tid == 127) sh_range[1] = e;   // thread 127 has max end

    const float scale = 0.1767766952966368811f;  // 1/sqrt(32)
    float4 qv[8];
    {
        const float* qp = qkv + (size_t)n * QKVDIM + h * HDIM;
#pragma unroll
        for (int i = 0; i < 8; i++) {
            float4 v = *(const float4*)(qp + i * 4);
            qv[i] = make_float4(v.x * scale, v.y * scale, v.z * scale, v.w * scale);
        }
    }

    float4 ov[8];
#pragma unroll
    for (int i = 0; i < 8; i++) ov[i] = make_float4(0.f, 0.f, 0.f, 0.f);
    float m = -1e30f, l = 0.f;

    __syncthreads();
    const int smin = sh_range[0];
    const int emax = sh_range[1];

    for (int kt = smin; kt < emax; kt += 64) {
        // cooperative 64x32 K/V tile load
#pragma unroll
        for (int i = 0; i < 4; i++) {
            int idx = tid + (i << 7);
            int r   = idx >> 3;
            int d4  = idx & 7;
            int kr  = kt + r;
            if (kr < NTOK) {
                const float* kp = qkv + (size_t)kr * QKVDIM + DMODEL + h * HDIM + (d4 << 2);
                *(float4*)&Ks[r][d4 << 2] = *(const float4*)kp;
                *(float4*)&Vs[r][d4 << 2] = *(const float4*)(kp + DMODEL);
            }
        }
        __syncthreads();

        int jlo = s - kt; if (jlo < 0)  jlo = 0;
        int jhi = e - kt; if (jhi > 64) jhi = 64;
        int j = jlo;
        for (; j + 1 < jhi; j += 2) {
            const float4* k0 = (const float4*)Ks[j];
            const float4* k1 = (const float4*)Ks[j + 1];
            float s00 = 0.f, s01 = 0.f, s02 = 0.f, s03 = 0.f;
            float s10 = 0.f, s11 = 0.f, s12 = 0.f, s13 = 0.f;
#pragma unroll
            for (int i = 0; i < 8; i++) {
                float4 a = qv[i], b0 = k0[i], b1 = k1[i];
                s00 += a.x * b0.x; s01 += a.y * b0.y;
                s02 += a.z * b0.z; s03 += a.w * b0.w;
                s10 += a.x * b1.x; s11 += a.y * b1.y;
                s12 += a.z * b1.z; s13 += a.w * b1.w;
            }
            float sc0 = (s00 + s01) + (s02 + s03);
            float sc1 = (s10 + s11) + (s12 + s13);
            float mn = fmaxf(m, fmaxf(sc0, sc1));
            if (mn > m) {
                float corr = __expf(m - mn);
                l *= corr;
#pragma unroll
                for (int i = 0; i < 8; i++) {
                    ov[i].x *= corr; ov[i].y *= corr;
                    ov[i].z *= corr; ov[i].w *= corr;
                }
                m = mn;
            }
            float p0 = __expf(sc0 - m);
            float p1 = __expf(sc1 - m);
            l += p0 + p1;
            const float4* v0 = (const float4*)Vs[j];
            const float4* v1 = (const float4*)Vs[j + 1];
#pragma unroll
            for (int i = 0; i < 8; i++) {
                float4 a = v0[i], c = v1[i];
                ov[i].x += p0 * a.x + p1 * c.x;
                ov[i].y += p0 * a.y + p1 * c.y;
                ov[i].z += p0 * a.z + p1 * c.z;
                ov[i].w += p0 * a.w + p1 * c.w;
            }
        }
        if (j < jhi) {   // odd tail
            const float4* k0 = (const float4*)Ks[j];
            float s00 = 0.f, s01 = 0.f, s02 = 0.f, s03 = 0.f;
#pragma unroll
            for (int i = 0; i < 8; i++) {
                float4 a = qv[i], b0 = k0[i];
                s00 += a.x * b0.x; s01 += a.y * b0.y;
                s02 += a.z * b0.z; s03 += a.w * b0.w;
            }
            float sc0 = (s00 + s01) + (s02 + s03);
            if (sc0 > m) {
                float corr = __expf(m - sc0);
                l *= corr;
#pragma unroll
                for (int i = 0; i < 8; i++) {
                    ov[i].x *= corr; ov[i].y *= corr;
                    ov[i].z *= corr; ov[i].w *= corr;
                }
                m = sc0;
            }
            float p0 = __expf(sc0 - m);
            l += p0;
            const float4* v0 = (const float4*)Vs[j];
#pragma unroll
            for (int i = 0; i < 8; i++) {
                float4 a = v0[i];
                ov[i].x += p0 * a.x; ov[i].y += p0 * a.y;
                ov[i].z += p0 * a.z; ov[i].w += p0 * a.w;
            }
        }
        __syncthreads();
    }

    const float inv = 1.f / l;   // l > 0: every row attends to itself
    float* op = out + (size_t)n * DMODEL + h * HDIM;
#pragma unroll
    for (int i = 0; i < 8; i++) {
        float4 v;
        v.x = ov[i].x * inv; v.y = ov[i].y * inv;
        v.z = ov[i].z * inv; v.w = ov[i].w * inv;
        *(float4*)(op + i * 4) = v;
    }
}

// ---------------------------------------------------------------------------
// Fused residual + LayerNorm. Warp per row.
// ---------------------------------------------------------------------------
__global__ __launch_bounds__(256) void ln_kernel(
    const float* __restrict__ x, const float* __restrict__ delta,
    const float* __restrict__ gamma, const float* __restrict__ beta,
    float* __restrict__ out)
{
    const int row  = blockIdx.x * 8 + (threadIdx.x >> 5);
    const int lane = threadIdx.x & 31;

    const float4* xp = (const float4*)(x + (size_t)row * DMODEL);
    const float4* dp = (const float4*)(delta + (size_t)row * DMODEL);

    float4 a = xp[lane],      bb = dp[lane];
    float4 v0 = make_float4(a.x + bb.x, a.y + bb.y, a.z + bb.z, a.w + bb.w);
    a = xp[lane + 32]; bb = dp[lane + 32];
    float4 v1 = make_float4(a.x + bb.x, a.y + bb.y, a.z + bb.z, a.w + bb.w);

    float sum = v0.x + v0.y + v0.z + v0.w + v1.x + v1.y + v1.z + v1.w;
#pragma unroll
    for (int off = 16; off; off >>= 1) sum += __shfl_xor_sync(0xffffffffu, sum, off);
    const float mean = sum * (1.f / 256.f);

    float sq = (v0.x - mean) * (v0.x - mean) + (v0.y - mean) * (v0.y - mean)
             + (v0.z - mean) * (v0.z - mean) + (v0.w - mean) * (v0.w - mean)
             + (v1.x - mean) * (v1.x - mean) + (v1.y - mean) * (v1.y - mean)
             + (v1.z - mean) * (v1.z - mean) + (v1.w - mean) * (v1.w - mean);
#pragma unroll
    for (int off = 16; off; off >>= 1) sq += __shfl_xor_sync(0xffffffffu, sq, off);
    const float rstd = rsqrtf(sq * (1.f / 256.f) + 1e-5f);

    float4 g = ((const float4*)gamma)[lane];
    float4 bt = ((const float4*)beta)[lane];
    float4 r0;
    r0.x = (v0.x - mean) * rstd * g.x + bt.x;
    r0.y = (v0.y - mean) * rstd * g.y + bt.y;
    r0.z = (v0.z - mean) * rstd * g.z + bt.z;
    r0.w = (v0.w - mean) * rstd * g.w + bt.w;
    g  = ((const float4*)gamma)[lane + 32];
    bt = ((const float4*)beta)[lane + 32];
    float4 r1;
    r1.x = (v1.x - mean) * rstd * g.x + bt.x;
    r1.y = (v1.y - mean) * rstd * g.y + bt.y;
    r1.z = (v1.z - mean) * rstd * g.z + bt.z;
    r1.w = (v1.w - mean) * rstd * g.w + bt.w;

    float4* op = (float4*)(out + (size_t)row * DMODEL);
    op[lane]      = r0;
    op[lane + 32] = r1;
}

// ---------------------------------------------------------------------------
// Launch (graph-capturable: kernel launches on default stream only)
// ---------------------------------------------------------------------------
extern "C" void kernel_launch(void* const* d_in, const int* in_sizes, int n_in,
                              void* d_out, int out_size)
{
    const float* slots  = (const float*)d_in[0];   // [1, 4096, 256]
    const int*   bidx   = (const int*)  d_in[1];   // [4096] sorted
    const float* w_in   = (const float*)d_in[2];   // [768, 256]
    const float* b_in   = (const float*)d_in[3];   // [768]
    const float* w_out  = (const float*)d_in[4];   // [256, 256]
    const float* b_out  = (const float*)d_in[5];   // [256]
    const float* ln_g   = (const float*)d_in[6];   // [256]
    const float* ln_b   = (const float*)d_in[7];   // [256]
    float*       out    = (float*)d_out;           // [1, 4096, 256]

    float *qkv, *attn, *delta;
    cudaGetSymbolAddress((void**)&qkv,   g_qkv);
    cudaGetSymbolAddress((void**)&attn,  g_attn);
    cudaGetSymbolAddress((void**)&delta, g_delta);

    cudaFuncSetAttribute(mma_gemm_kernel,
                         cudaFuncAttributeMaxDynamicSharedMemorySize, GM_SMEM);

    // 1) QKV = x @ w_in^T + b_in   [4096, 768]  (HMMA bf16x3, fused split)
    {
        dim3 grid(QKVDIM / 64, NTOK / 128);
        mma_gemm_kernel<<<grid, 256, GM_SMEM>>>(slots, w_in, b_in, qkv, QKVDIM);
    }
    // 2) Block-diagonal attention   [4096, 256]
    {
        dim3 grid(NTOK / 128, NHEAD);
        attn_kernel<<<grid, 128>>>(qkv, bidx, attn);
    }
    // 3) delta = attn @ w_out^T + b_out   [4096, 256]
    {
        dim3 grid(DMODEL / 64, NTOK / 128);
        mma_gemm_kernel<<<grid, 256, GM_SMEM>>>(attn, w_out, b_out, delta, DMODEL);
    }
    // 4) out = LayerNorm(x + delta)
    ln_kernel<<<NTOK / 8, 256>>>(slots, delta, ln_g, ln_b, out);
}